// round 4
// baseline (speedup 1.0000x reference)
#include <cuda_runtime.h>
#include <math.h>

// DTW 2048x2048, out = sqrt(DTW[N-1][N-1]).
// v[i][j] = (x[i]-y[j])^2 + min(up,left,diag); border v[-1][-1]=0 else inf.
//
// Multi-SM systolic pipeline: 8-CTA cluster x 64 threads = 512 stages,
// stage t owns cols [4t,4t+4), rows in chunks of 4. NO barriers:
//  - intra-warp edges: __shfl_up_sync (previous iteration's vout)
//  - cross-warp edges: producer lane31 pushes float4 + release-flag into the
//    consumer warp's smem via mapa/st.shared::cluster; consumer warp does a
//    uniform local acquire-poll. Full 512-slot arrays => no ring/overwrite.
//  - fill phase uses INF edges (poll only on real steps) so junk tiles keep
//    all-INF carries -> bitwise-identical results to the reference recurrence.

#define NCTA 8
#define WPB  2
#define NT   (WPB * 32)        // 64 threads / CTA
#define TTOT (NCTA * NT)       // 512 stages
#define NC   4
#define NR   4
#define LEN  2048
#define NK   (LEN / NR)        // 512 chunks
#define NS   (TTOT - 1 + NK)   // 1023 steps

__global__ __launch_bounds__(NT, 1) __cluster_dims__(NCTA, 1, 1)
void dtw_kernel(const float* __restrict__ x,
                const float* __restrict__ y,
                float* __restrict__ out)
{
    __shared__ float  xs[LEN];            // 8 KB
    __shared__ float4 edata[WPB][NK];     // 16 KB  consumer edge slots
    __shared__ unsigned eflag[WPB][NK];   // 4 KB   ready flags

    const int tid  = threadIdx.x;
    const int lane = tid & 31;
    const int wid  = tid >> 5;
    unsigned rank;
    asm("mov.u32 %0, %%cluster_ctarank;" : "=r"(rank));
    const int tg    = (int)rank * NT + tid;   // global stage 0..511
    const int wbase = tg - lane;              // warp's first stage
    const float INF = __int_as_float(0x7f800000);

    for (int i = tid; i < LEN / 4; i += NT)
        reinterpret_cast<float4*>(xs)[i] = reinterpret_cast<const float4*>(x)[i];
    for (int i = tid; i < WPB * NK; i += NT)
        reinterpret_cast<unsigned*>(eflag)[i] = 0u;
    __syncthreads();
    asm volatile("barrier.cluster.arrive.aligned;" ::: "memory");
    asm volatile("barrier.cluster.wait.aligned;" ::: "memory");

    const float4 yv = reinterpret_cast<const float4*>(y)[tg];
    const float yc[NC] = {yv.x, yv.y, yv.z, yv.w};
    float prev[NC] = {INF, INF, INF, INF};
    float diag_edge = (tg == 0) ? 0.0f : INF;
    float4 vout = make_float4(INF, INF, INF, INF);

    // Consumer-side local addresses (this warp's slots).
    const unsigned cons_flag = (unsigned)__cvta_generic_to_shared(&eflag[wid][0]);
    const unsigned cons_data = (unsigned)__cvta_generic_to_shared(&edata[wid][0]);
    // Producer-side target: stage tg feeds tg+1 -> consumer warp is wid+1
    // (same CTA) or wid 0 of rank+1 (remote). mapa(same rank) == identity.
    unsigned prod_data, prod_flag;
    {
        const int cw = (wid + 1) % WPB;
        unsigned ld_ = (unsigned)__cvta_generic_to_shared(&edata[cw][0]);
        unsigned lf_ = (unsigned)__cvta_generic_to_shared(&eflag[cw][0]);
        unsigned trank = (wid == WPB - 1) ? (rank + 1u) : rank;
        if (trank >= NCTA) trank = rank;  // last stage: unused, keep mapa valid
        asm("mapa.shared::cluster.u32 %0, %1, %2;" : "=r"(prod_data) : "r"(ld_), "r"(trank));
        asm("mapa.shared::cluster.u32 %0, %1, %2;" : "=r"(prod_flag) : "r"(lf_), "r"(trank));
    }
    const bool is_prod = (lane == 31) && (tg != TTOT - 1);
    const bool do_poll = (wbase != 0);

    for (int s = 0; s < NS; s++) {
        // Intra-warp edges: lane l-1's vout from the previous step.
        float4 e;
        e.x = __shfl_up_sync(0xffffffffu, vout.x, 1);
        e.y = __shfl_up_sync(0xffffffffu, vout.y, 1);
        e.z = __shfl_up_sync(0xffffffffu, vout.z, 1);
        e.w = __shfl_up_sync(0xffffffffu, vout.w, 1);

        // Lane 0's edge: polled remote edge on real steps only; INF otherwise
        // (fill keeps carries at INF, drain values are never consumed).
        float4 m = make_float4(INF, INF, INF, INF);
        const int k0 = s - wbase;                     // warp-uniform
        if (do_poll && (unsigned)k0 < (unsigned)NK) { // warp-uniform branch
            const unsigned fa = cons_flag + ((unsigned)k0 << 2);
            unsigned f;
            do {
                asm volatile("ld.acquire.cluster.shared.u32 %0, [%1];"
                             : "=r"(f) : "r"(fa) : "memory");
            } while (!f);
            const unsigned da = cons_data + ((unsigned)k0 << 4);
            asm volatile("ld.shared.v4.f32 {%0,%1,%2,%3}, [%4];"
                         : "=f"(m.x), "=f"(m.y), "=f"(m.z), "=f"(m.w)
                         : "r"(da) : "memory");
        }
        if (lane == 0) e = m;

        int k = s - tg;
        k = max(0, min(k, NK - 1));  // clamp: fill=INF-prop, drain=unconsumed
        const float4 xv = *reinterpret_cast<const float4*>(xs + (k << 2));
        const float xr[NR] = {xv.x, xv.y, xv.z, xv.w};
        const float er[NR] = {e.x, e.y, e.z, e.w};

        float left[NR], dgr[NR];
        left[0] = er[0]; left[1] = er[1]; left[2] = er[2]; left[3] = er[3];
        dgr[0]  = diag_edge; dgr[1] = er[0]; dgr[2] = er[1]; dgr[3] = er[2];
        diag_edge = er[NR - 1];

        // Stagger-2 intra-tile wavefront: 4 concurrent dependency chains.
        #pragma unroll
        for (int jj = 0; jj < NC + 2 * (NR - 1); jj++) {
            #pragma unroll
            for (int i = 0; i < NR; i++) {
                const int j = jj - 2 * i;
                if (j >= 0 && j < NC) {
                    float d  = xr[i] - yc[j];
                    float up = prev[j];
                    float mm = fminf(fminf(up, dgr[i]), left[i]);
                    float v  = fmaf(d, d, mm);
                    dgr[i]  = up;
                    prev[j] = v;
                    left[i] = v;
                }
            }
        }
        vout = make_float4(left[0], left[1], left[2], left[3]);

        // Producer push: data then release-flag, real chunks only (so drain
        // never overwrites slot NK-1 while the consumer may read it).
        const int kr = s - tg;
        if (is_prod && (unsigned)kr < (unsigned)NK) {
            const unsigned da = prod_data + ((unsigned)kr << 4);
            const unsigned fa = prod_flag + ((unsigned)kr << 2);
            asm volatile("st.shared::cluster.v4.f32 [%0], {%1,%2,%3,%4};"
                         :: "r"(da), "f"(vout.x), "f"(vout.y), "f"(vout.z), "f"(vout.w)
                         : "memory");
            asm volatile("st.release.cluster.shared::cluster.u32 [%0], %1;"
                         :: "r"(fa), "r"(1u) : "memory");
        }
    }

    // Stage 511's final step (s = NS-1) computed chunk 511: vout.w = v[2047][2047].
    if (tg == TTOT - 1) out[0] = sqrtf(vout.w);
}

extern "C" void kernel_launch(void* const* d_in, const int* in_sizes, int n_in,
                              void* d_out, int out_size)
{
    const float* x = (const float*)d_in[0];
    const float* y = (const float*)d_in[1];
    float* out = (float*)d_out;
    (void)in_sizes; (void)n_in; (void)out_size;
    dtw_kernel<<<NCTA, NT>>>(x, y, out);
}

// round 5
// speedup vs baseline: 2.8100x; 2.8100x over previous
#include <cuda_runtime.h>
#include <math.h>

// DTW 2048x2048, out = sqrt(DTW[N-1][N-1]).
// v[i][j] = (x[i]-y[j])^2 + min(up,left,diag); border v[-1][-1]=0 else inf.
//
// Single-CTA thread-skewed systolic wavefront, reshaped for issue balance:
//  - NT=128 threads (4 warps -> exactly 1 warp per SMSP: no SMSP ever has
//    two active warps, so the per-step issue floor never doubles).
//  - Each thread owns NC=16 columns; rows stream in NR=4 chunks; NS=639 steps.
//  - Stagger-1 intra-tile schedule (cell (i,j) in slot i+j): left/up deps one
//    slot earlier, diag two -> 4 concurrent chains, tile critical path ~190cyc.
//  - Activity guard kept (R3 lesson: junk tiles waste issue slots).
//  - Plain __syncthreads kept (R4 lesson: cluster-scope sync is 5x worse).
// Per-cell arithmetic identical to R1 -> bitwise-identical result.

#define NT   128
#define NC   16
#define NR   4
#define LEN  2048
#define NK   (LEN / NR)     // 512
#define NS   (NT - 1 + NK)  // 639

__global__ __launch_bounds__(NT, 1)
void dtw_kernel(const float* __restrict__ x,
                const float* __restrict__ y,
                float* __restrict__ out)
{
    __shared__ float  xs[LEN];          // 8 KB
    __shared__ float4 buf[2][NT + 1];   // edge double-buffer, slot 0 == +inf

    const int   t   = threadIdx.x;
    const float INF = __int_as_float(0x7f800000);

    // Preload x (visible after first barrier).
    {
        const float4* x4  = reinterpret_cast<const float4*>(x);
        float4*       xs4 = reinterpret_cast<float4*>(xs);
        #pragma unroll
        for (int i = t; i < LEN / 4; i += NT) xs4[i] = x4[i];
    }
    // Edge buffers start at INF; slot 0 is never overwritten and provides the
    // global left boundary (column -1 = +inf).
    buf[0][t] = make_float4(INF, INF, INF, INF);
    buf[1][t] = make_float4(INF, INF, INF, INF);
    if (t == 0) {
        buf[0][NT] = make_float4(INF, INF, INF, INF);
        buf[1][NT] = make_float4(INF, INF, INF, INF);
    }

    // This thread's 16 y columns.
    float yc[NC];
    {
        const float4* y4 = reinterpret_cast<const float4*>(y + t * NC);
        #pragma unroll
        for (int q = 0; q < NC / 4; q++) {
            float4 v = y4[q];
            yc[4 * q + 0] = v.x; yc[4 * q + 1] = v.y;
            yc[4 * q + 2] = v.z; yc[4 * q + 3] = v.w;
        }
    }

    float prev[NC];
    #pragma unroll
    for (int c = 0; c < NC; c++) prev[c] = INF;

    float  diag_edge = (t == 0) ? 0.0f : INF;
    float4 vout      = make_float4(INF, INF, INF, INF);

    for (int s = 0; s < NS; s++) {
        __syncthreads();
        const int k = s - t;
        if (k >= 0 && k < NK) {
            // Left edge: thread t-1's previous-step output (slot t; slot 0 = INF).
            const float4 ev = buf[(s - 1) & 1][t];
            const float4 xv = *reinterpret_cast<const float4*>(xs + (k << 2));

            const float xr[NR] = {xv.x, xv.y, xv.z, xv.w};
            const float e[NR]  = {ev.x, ev.y, ev.z, ev.w};

            float left[NR], dgr[NR];
            left[0] = e[0]; left[1] = e[1]; left[2] = e[2]; left[3] = e[3];
            dgr[0]  = diag_edge; dgr[1] = e[0]; dgr[2] = e[1]; dgr[3] = e[2];
            diag_edge = e[NR - 1];

            // Stagger-1 wavefront: slot jj computes cells (i, jj-i).
            #pragma unroll
            for (int jj = 0; jj < NC + NR - 1; jj++) {
                #pragma unroll
                for (int i = 0; i < NR; i++) {
                    const int j = jj - i;          // compile-time after unroll
                    if (j >= 0 && j < NC) {
                        float d  = xr[i] - yc[j];
                        float up = prev[j];
                        float m  = fminf(fminf(up, dgr[i]), left[i]);
                        float v  = fmaf(d, d, m);
                        dgr[i]  = up;
                        prev[j] = v;
                        left[i] = v;
                    }
                }
            }

            vout = make_float4(left[0], left[1], left[2], left[3]);
            buf[s & 1][t + 1] = vout;
        }
    }

    // Thread 127's final step (s = NS-1, chunk NK-1): vout.w = v[2047][2047].
    if (t == NT - 1) out[0] = sqrtf(vout.w);
}

extern "C" void kernel_launch(void* const* d_in, const int* in_sizes, int n_in,
                              void* d_out, int out_size)
{
    const float* x = (const float*)d_in[0];
    const float* y = (const float*)d_in[1];
    float* out = (float*)d_out;
    (void)in_sizes; (void)n_in; (void)out_size;
    dtw_kernel<<<1, NT>>>(x, y, out);
}